// round 15
// baseline (speedup 1.0000x reference)
#include <cuda_runtime.h>
#include <math.h>

#define BB 2
#define CC 8
#define MM 8
#define HH 8
#define FF 256
#define WW 512
#define HD 32
#define BMFW (BB*MM*FF*WW)   // 2,097,152
#define NT  (BB*MM*HH)       // 128 attention tiles
#define WW2 (WW*WW)          // 262144

// ---- scratch (static device memory; no allocation) ----
__device__ float g_c1[3*BMFW];     // conv1 outputs for q,k,v
__device__ float g_lin[3*BMFW];    // lin outputs q,k,v
__device__ float g_qkv[3*BMFW];    // q,k,v post conv2(+rotary), layout [b][m][f][w]
__device__ float g_at[BMFW];       // attention out, layout [b][m][w][f]
__device__ float g_rotc[16*WW];
__device__ float g_rots[16*WW];

// ============================================================
// Kernel 0: rotary table
// ============================================================
__global__ void rot_table_kernel()
{
    int i = blockIdx.x, w = threadIdx.x;
    float invf = expf(-(float)i * (9.210340371976184f / 16.0f));
    float sn, cs;
    sincosf((float)w * invf, &sn, &cs);
    g_rotc[i*WW + w] = cs;
    g_rots[i*WW + w] = sn;
}

// ============================================================
// Kernel 1: 3x3 conv, 8->8 ch, all three projections at once.
// ============================================================
__global__ __launch_bounds__(256) void conv1_kernel(
    const float* __restrict__ x,
    const float* __restrict__ wq,
    const float* __restrict__ wk,
    const float* __restrict__ wv)
{
    int f = blockIdx.x, b = blockIdx.y;
    extern __shared__ float sm[];
    float* xs = sm;                      // [3][CC][WW+2]
    float* wt = sm + 3*CC*(WW+2);        // [3][MM][CC][9]
    int tid = threadIdx.x;

    for (int idx = tid; idx < 3*CC*(WW+2); idx += 256) {
        int r   = idx / (CC*(WW+2));
        int rem = idx % (CC*(WW+2));
        int c   = rem / (WW+2);
        int w   = rem % (WW+2) - 1;
        int fr  = f + r - 1;
        float v = 0.f;
        if (fr >= 0 && fr < FF && w >= 0 && w < WW)
            v = x[((b*CC + c)*FF + fr)*WW + w];
        xs[idx] = v;
    }
    for (int idx = tid; idx < MM*CC*9; idx += 256) {
        wt[idx]              = wq[idx];
        wt[idx +   MM*CC*9]  = wk[idx];
        wt[idx + 2*MM*CC*9]  = wv[idx];
    }
    __syncthreads();

    for (int o = tid; o < 3*MM*WW; o += 256) {
        int p = o / (MM*WW);
        int m = (o / WW) % MM;
        int w = o % WW;
        const float* wpt = wt + (p*MM + m)*CC*9;
        float acc = 0.f;
        #pragma unroll
        for (int c = 0; c < CC; c++) {
            #pragma unroll
            for (int r = 0; r < 3; r++) {
                const float* xr = xs + (r*CC + c)*(WW+2) + w;
                acc += xr[0]*wpt[c*9 + r*3 + 0];
                acc += xr[1]*wpt[c*9 + r*3 + 1];
                acc += xr[2]*wpt[c*9 + r*3 + 2];
            }
        }
        g_c1[p*BMFW + ((b*MM + m)*FF + f)*WW + w] = acc;
    }
}

// ============================================================
// Kernel 2: batched GEMM, 128x64 tiles, 8x4 microtile.
// ============================================================
__global__ __launch_bounds__(256) void gemm_lin_kernel(
    const float* __restrict__ Aq,
    const float* __restrict__ Ak,
    const float* __restrict__ Av)
{
    __shared__ float As[128*17];
    __shared__ float Bs[16*64];
    int z = blockIdx.z;
    int p = z >> 4;
    int n = z & 15;
    int m = n % MM;
    int g0 = blockIdx.y * 128, w0 = blockIdx.x * 64;
    const float* A = (p == 0) ? Aq : (p == 1) ? Ak : Av;
    const float* Ap = A + m*FF*FF;
    const float* Bp = g_c1  + (size_t)p*BMFW + (size_t)n*FF*WW;
    float*       Cp = g_lin + (size_t)p*BMFW + (size_t)n*FF*WW;
    int tx = threadIdx.x, ty = threadIdx.y;
    int tid = ty*16 + tx;

    float acc[8][4] = {};
    for (int f0 = 0; f0 < FF; f0 += 16) {
        #pragma unroll
        for (int u = 0; u < 2; u++) {
            int idx = tid + u*256;
            int r = idx >> 2;
            int c4 = (idx & 3) * 4;
            float4 a4 = *(const float4*)(Ap + (g0+r)*FF + f0 + c4);
            As[r*17 + c4+0] = a4.x; As[r*17 + c4+1] = a4.y;
            As[r*17 + c4+2] = a4.z; As[r*17 + c4+3] = a4.w;
        }
        {
            int fl = tid >> 4;
            int wl = (tid & 15) * 4;
            *(float4*)(Bs + fl*64 + wl) =
                *(const float4*)(Bp + (f0+fl)*WW + w0 + wl);
        }
        __syncthreads();
        #pragma unroll
        for (int k = 0; k < 16; k++) {
            float a[8];
            #pragma unroll
            for (int i = 0; i < 8; i++) a[i] = As[(ty*8+i)*17 + k];
            float4 b4 = *(const float4*)(Bs + k*64 + tx*4);
            float bf[4] = {b4.x, b4.y, b4.z, b4.w};
            #pragma unroll
            for (int i = 0; i < 8; i++)
                #pragma unroll
                for (int j = 0; j < 4; j++)
                    acc[i][j] += a[i]*bf[j];
        }
        __syncthreads();
    }
    #pragma unroll
    for (int i = 0; i < 8; i++) {
        float4 o4 = make_float4(acc[i][0], acc[i][1], acc[i][2], acc[i][3]);
        *(float4*)(Cp + (g0 + ty*8 + i)*WW + w0 + tx*4) = o4;
    }
}

// ============================================================
// Kernel 3: 1x3 conv across M + rotary, all 3 projections (z).
// ============================================================
__global__ __launch_bounds__(256) void conv2_rot_kernel(
    const float* __restrict__ wq2,
    const float* __restrict__ wk2,
    const float* __restrict__ wv2)
{
    int e = blockIdx.x, b = blockIdx.y, p = blockIdx.z;
    int f0 = 2*e;
    int apply_rot = (p < 2);
    const float* wc2 = (p == 0) ? wq2 : (p == 1) ? wk2 : wv2;
    const float* src = g_lin + (size_t)p*BMFW;
    float*       dst = g_qkv + (size_t)p*BMFW;

    __shared__ float hs[2*MM*(WW+2)];
    __shared__ float wt[MM*MM*3];
    __shared__ float rc[WW], rs[WW];
    int tid = threadIdx.x;

    for (int idx = tid; idx < 2*MM*(WW+2); idx += 256) {
        int rr  = idx / (MM*(WW+2));
        int rem = idx % (MM*(WW+2));
        int mm  = rem / (WW+2);
        int w   = rem % (WW+2) - 1;
        float v = 0.f;
        if (w >= 0 && w < WW)
            v = src[((b*MM + mm)*FF + f0 + rr)*WW + w];
        hs[idx] = v;
    }
    for (int idx = tid; idx < MM*MM*3; idx += 256) wt[idx] = wc2[idx];
    if (apply_rot) {
        int i = e % (HD/2);
        for (int w = tid; w < WW; w += 256) {
            rc[w] = g_rotc[i*WW + w];
            rs[w] = g_rots[i*WW + w];
        }
    }
    __syncthreads();

    for (int o = tid; o < MM*(WW/4); o += 256) {
        int m  = o >> 7;            // WW/4 = 128
        int w4 = (o & 127) * 4;
        float c0[4] = {0.f,0.f,0.f,0.f};
        float c1[4] = {0.f,0.f,0.f,0.f};
        #pragma unroll
        for (int mm = 0; mm < MM; mm++) {
            float k0 = wt[(m*MM+mm)*3+0];
            float k1 = wt[(m*MM+mm)*3+1];
            float k2 = wt[(m*MM+mm)*3+2];
            const float* h0 = hs + mm*(WW+2) + w4;
            const float* h1 = hs + (MM+mm)*(WW+2) + w4;
            float a0=h0[0],a1=h0[1],a2=h0[2],a3=h0[3],a4=h0[4],a5=h0[5];
            c0[0] += a0*k0 + a1*k1 + a2*k2;
            c0[1] += a1*k0 + a2*k1 + a3*k2;
            c0[2] += a2*k0 + a3*k1 + a4*k2;
            c0[3] += a3*k0 + a4*k1 + a5*k2;
            float e0=h1[0],e1=h1[1],e2=h1[2],e3=h1[3],e4=h1[4],e5=h1[5];
            c1[0] += e0*k0 + e1*k1 + e2*k2;
            c1[1] += e1*k0 + e2*k1 + e3*k2;
            c1[2] += e2*k0 + e3*k1 + e4*k2;
            c1[3] += e3*k0 + e4*k1 + e5*k2;
        }
        float4 o0, o1;
        float* po0 = (float*)&o0;
        float* po1 = (float*)&o1;
        if (apply_rot) {
            #pragma unroll
            for (int u = 0; u < 4; u++) {
                float cs = rc[w4+u], sn = rs[w4+u];
                po0[u] = c0[u]*cs - c1[u]*sn;
                po1[u] = c1[u]*cs + c0[u]*sn;
            }
        } else {
            #pragma unroll
            for (int u = 0; u < 4; u++) { po0[u] = c0[u]; po1[u] = c1[u]; }
        }
        *(float4*)(dst + ((size_t)(b*MM + m)*FF + f0    )*WW + w4) = o0;
        *(float4*)(dst + ((size_t)(b*MM + m)*FF + f0 + 1)*WW + w4) = o1;
    }
}

// ============================================================
// Kernel 4: FUSED attention, 512 threads (16 warps), all fp32.
// S GEMM: 8x4 microtile (warp = 8 rows, lane = 4 cols).
// PV: d = lane (conflict-free V), 8 rows/thread, full j coverage
// per thread -> no cross-thread reduction; rowsum via shuffles.
// ============================================================
#define PPAD 132

__global__ __launch_bounds__(512, 1) void attn_fused_kernel(
    const float* __restrict__ prev_qk,
    float* __restrict__ qk_out)
{
    int rb = blockIdx.x, t = blockIdx.y;
    int r0 = rb * 128;
    int h = t % HH, m = (t / HH) % MM, b = t / (HH*MM);

    extern __shared__ float smx[];
    float* Qt  = smx;                 // [32][PPAD] 16.9 KB
    float* Kt  = Qt  + 32*PPAD;       // [32][PPAD] 16.9 KB
    float* Pch = Kt  + 32*PPAD;       // [128][PPAD] 67.6 KB
    float* Vs  = Pch + 128*PPAD;      // [512][32]   65.5 KB

    int tid  = threadIdx.x;
    int lane = tid & 31;
    int ty   = tid >> 5;              // warp id = row group [0,16)

    const float* Qb = g_qkv + 0*BMFW + ((b*MM+m)*FF + h*HD)*WW;
    const float* Kb = g_qkv + 1*BMFW + ((b*MM+m)*FF + h*HD)*WW;
    const float* Vb = g_qkv + 2*BMFW + ((b*MM+m)*FF + h*HD)*WW;
    const float* Pq   = prev_qk + (size_t)t*WW2;
    float*       Sout = qk_out  + (size_t)t*WW2;
    float*       At   = g_at + (size_t)(b*MM+m)*WW*FF + h*HD;

    // load Q^T subtile Qt[k][r] and V as Vs[j][d]
    #pragma unroll
    for (int u = 0; u < 2; u++) {
        int fid = tid + u*512;        // [0,1024)
        int d   = fid >> 5;
        int c4  = (fid & 31) * 4;
        *(float4*)(Qt + d*PPAD + c4) = *(const float4*)(Qb + d*WW + r0 + c4);
    }
    for (int idx = tid; idx < HD*WW; idx += 512) {
        int d = idx >> 9, w = idx & 511;
        Vs[w*32 + d] = Vb[d*WW + w];
    }

    float rsum[8];
    float pv[8];
    #pragma unroll
    for (int i = 0; i < 8; i++) { rsum[i] = 0.f; pv[i] = 0.f; }

    const float scale = 0.0625f;

    for (int cc = 0; cc < 4; cc++) {
        int j0 = cc * 128;
        __syncthreads();   // Qt/Vs ready (cc=0); PV(cc-1) done with Pch/Kt

        // ---- Kt chunk load ----
        #pragma unroll
        for (int u = 0; u < 2; u++) {
            int fid = tid + u*512;
            int d   = fid >> 5;
            int c4  = (fid & 31) * 4;
            *(float4*)(Kt + d*PPAD + c4) = *(const float4*)(Kb + d*WW + j0 + c4);
        }
        __syncthreads();

        // ---- S GEMM: 128x128, K=32, 8x4 microtile ----
        float acc[8][4];
        #pragma unroll
        for (int i = 0; i < 8; i++)
            #pragma unroll
            for (int j = 0; j < 4; j++) acc[i][j] = 0.f;

        #pragma unroll 4
        for (int k = 0; k < 32; k++) {
            float4 a0 = *(const float4*)(Qt + k*PPAD + ty*8);
            float4 a1 = *(const float4*)(Qt + k*PPAD + ty*8 + 4);
            float4 b4 = *(const float4*)(Kt + k*PPAD + lane*4);
            float av[8] = {a0.x,a0.y,a0.z,a0.w,a1.x,a1.y,a1.z,a1.w};
            float bv[4] = {b4.x,b4.y,b4.z,b4.w};
            #pragma unroll
            for (int i = 0; i < 8; i++)
                #pragma unroll
                for (int j = 0; j < 4; j++)
                    acc[i][j] += av[i]*bv[j];
        }

        // ---- epilogue: prev LDG, Sout, exp -> Pch, rowsum ----
        #pragma unroll
        for (int i = 0; i < 8; i++) {
            size_t rowoff = (size_t)(r0 + ty*8 + i)*WW + j0 + lane*4;
            float4 pq4 = __ldg((const float4*)(Pq + rowoff));
            float4 s4;
            s4.x = fmaf(acc[i][0], scale, pq4.x);
            s4.y = fmaf(acc[i][1], scale, pq4.y);
            s4.z = fmaf(acc[i][2], scale, pq4.z);
            s4.w = fmaf(acc[i][3], scale, pq4.w);
            *(float4*)(Sout + rowoff) = s4;
            float4 e4;
            e4.x = __expf(s4.x); e4.y = __expf(s4.y);
            e4.z = __expf(s4.z); e4.w = __expf(s4.w);
            *(float4*)(Pch + (ty*8 + i)*PPAD + lane*4) = e4;
            rsum[i] += e4.x + e4.y + e4.z + e4.w;
        }
        __syncthreads();   // Pch ready

        // ---- PV: d = lane, rows ty*8..+8, all 128 j of chunk ----
        {
            const float* vp = Vs + j0*32 + lane;
            #pragma unroll 2
            for (int jj = 0; jj < 128; jj += 4) {
                float4 p[8];
                #pragma unroll
                for (int i = 0; i < 8; i++)
                    p[i] = *(const float4*)(Pch + (ty*8+i)*PPAD + jj);
                float v0 = vp[(jj+0)*32];
                float v1 = vp[(jj+1)*32];
                float v2 = vp[(jj+2)*32];
                float v3 = vp[(jj+3)*32];
                #pragma unroll
                for (int i = 0; i < 8; i++)
                    pv[i] += p[i].x*v0 + p[i].y*v1 + p[i].z*v2 + p[i].w*v3;
            }
        }
    }

    // ---- rowsum warp-reduce, normalize, store A (d = lane) ----
    #pragma unroll
    for (int i = 0; i < 8; i++) {
        float s = rsum[i];
        #pragma unroll
        for (int o = 16; o > 0; o >>= 1)
            s += __shfl_xor_sync(0xffffffffu, s, o);
        At[(size_t)(r0 + ty*8 + i)*FF + lane] = pv[i] / s;
    }
}

// ============================================================
// Kernel 5: out projection, 128x64 tiles, 8x4 microtile.
// ============================================================
__global__ __launch_bounds__(256) void gemm_out_kernel(
    const float* __restrict__ A,
    const float* __restrict__ Bt,
    float* __restrict__ Cx)
{
    __shared__ float As[128*17];
    __shared__ float Bs[64*17];
    int n = blockIdx.z;
    int m = n % MM;
    int g0 = blockIdx.y * 128, w0 = blockIdx.x * 64;
    const float* Ap = A  + m*FF*FF;
    const float* Bp = Bt + (size_t)n*WW*FF;
    int tx = threadIdx.x, ty = threadIdx.y;
    int tid = ty*16 + tx;

    float acc[8][4] = {};
    for (int f0 = 0; f0 < FF; f0 += 16) {
        #pragma unroll
        for (int u = 0; u < 2; u++) {
            int idx = tid + u*256;
            int r = idx >> 2;
            int c4 = (idx & 3) * 4;
            float4 a4 = *(const float4*)(Ap + (g0+r)*FF + f0 + c4);
            As[r*17 + c4+0] = a4.x; As[r*17 + c4+1] = a4.y;
            As[r*17 + c4+2] = a4.z; As[r*17 + c4+3] = a4.w;
        }
        {
            int wl = tid >> 2;
            int c4 = (tid & 3) * 4;
            float4 b4 = *(const float4*)(Bp + (size_t)(w0+wl)*FF + f0 + c4);
            Bs[wl*17 + c4+0] = b4.x; Bs[wl*17 + c4+1] = b4.y;
            Bs[wl*17 + c4+2] = b4.z; Bs[wl*17 + c4+3] = b4.w;
        }
        __syncthreads();
        #pragma unroll
        for (int k = 0; k < 16; k++) {
            float a[8], bf[4];
            #pragma unroll
            for (int i = 0; i < 8; i++) a[i]  = As[(ty*8+i)*17 + k];
            #pragma unroll
            for (int j = 0; j < 4; j++) bf[j] = Bs[(tx*4+j)*17 + k];
            #pragma unroll
            for (int i = 0; i < 8; i++)
                #pragma unroll
                for (int j = 0; j < 4; j++)
                    acc[i][j] += a[i]*bf[j];
        }
        __syncthreads();
    }
    #pragma unroll
    for (int i = 0; i < 8; i++) {
        float4 o4 = make_float4(acc[i][0], acc[i][1], acc[i][2], acc[i][3]);
        *(float4*)(Cx + ((size_t)n*FF + g0 + ty*8 + i)*WW + w0 + tx*4) = o4;
    }
}

// ============================================================
extern "C" void kernel_launch(void* const* d_in, const int* in_sizes, int n_in,
                              void* d_out, int out_size)
{
    const float* x       = (const float*)d_in[0];
    const float* prev_qk = (const float*)d_in[1];
    const float* ow      = (const float*)d_in[11];

    float* out_ptr = (float*)d_out;                // (B,M,F,W) first
    float* qk_ptr  = out_ptr + (size_t)BMFW;       // (B,M,H,W,W) second

    float* p_at;
    cudaGetSymbolAddress((void**)&p_at, g_at);

    // rotary table
    rot_table_kernel<<<16, WW>>>();

    // conv1
    int conv1_smem = (3*CC*(WW+2) + 3*MM*CC*9) * 4;
    cudaFuncSetAttribute(conv1_kernel,
        cudaFuncAttributeMaxDynamicSharedMemorySize, conv1_smem);
    conv1_kernel<<<dim3(FF, BB), 256, conv1_smem>>>(
        x, (const float*)d_in[2], (const float*)d_in[5], (const float*)d_in[8]);

    // lin GEMMs
    gemm_lin_kernel<<<dim3(WW/64, FF/128, 3*BB*MM), dim3(16,16)>>>(
        (const float*)d_in[3], (const float*)d_in[6], (const float*)d_in[9]);

    // conv2 (+rotary)
    conv2_rot_kernel<<<dim3(FF/2, BB, 3), 256>>>(
        (const float*)d_in[4], (const float*)d_in[7], (const float*)d_in[10]);

    // fused attention (all fp32; 512 threads)
    int attn_smem = (32*PPAD + 32*PPAD + 128*PPAD + 512*32) * 4;  // 166912 B
    cudaFuncSetAttribute(attn_fused_kernel,
        cudaFuncAttributeMaxDynamicSharedMemorySize, attn_smem);
    attn_fused_kernel<<<dim3(4, NT), 512, attn_smem>>>(prev_qk, qk_ptr);

    // output projection
    gemm_out_kernel<<<dim3(WW/64, FF/128, BB*MM), dim3(16,16)>>>(ow, p_at, out_ptr);
}

// round 16
// speedup vs baseline: 1.1947x; 1.1947x over previous
#include <cuda_runtime.h>
#include <math.h>

#define BB 2
#define CC 8
#define MM 8
#define HH 8
#define FF 256
#define WW 512
#define HD 32
#define BMFW (BB*MM*FF*WW)   // 2,097,152
#define NT  (BB*MM*HH)       // 128 attention tiles
#define WW2 (WW*WW)          // 262144

// ---- scratch (static device memory; no allocation) ----
__device__ float g_c1[3*BMFW];     // conv1 outputs for q,k,v
__device__ float g_lin[3*BMFW];    // lin outputs q,k,v
__device__ float g_qkv[3*BMFW];    // q,k,v post conv2(+rotary), layout [b][m][f][w]
__device__ float g_at[BMFW];       // attention out, layout [b][m][w][f]
__device__ float g_rotc[16*WW];
__device__ float g_rots[16*WW];

// ---- tf32 helpers ----
__device__ __forceinline__ float to_tf32(float x) {
    float r;
    asm("cvt.rna.tf32.f32 %0, %1;" : "=f"(r) : "f"(x));
    return r;
}
__device__ __forceinline__ void mma_tf32(float* c, const unsigned* a,
                                         unsigned b0, unsigned b1) {
    asm volatile(
        "mma.sync.aligned.m16n8k8.row.col.f32.tf32.tf32.f32 "
        "{%0,%1,%2,%3}, {%4,%5,%6,%7}, {%8,%9}, {%0,%1,%2,%3};"
        : "+f"(c[0]), "+f"(c[1]), "+f"(c[2]), "+f"(c[3])
        : "r"(a[0]), "r"(a[1]), "r"(a[2]), "r"(a[3]), "r"(b0), "r"(b1));
}

// ============================================================
// Kernel 0: rotary table
// ============================================================
__global__ void rot_table_kernel()
{
    int i = blockIdx.x, w = threadIdx.x;
    float invf = expf(-(float)i * (9.210340371976184f / 16.0f));
    float sn, cs;
    sincosf((float)w * invf, &sn, &cs);
    g_rotc[i*WW + w] = cs;
    g_rots[i*WW + w] = sn;
}

// ============================================================
// Kernel 1: 3x3 conv, 8->8 ch, all three projections at once.
// ============================================================
__global__ __launch_bounds__(256) void conv1_kernel(
    const float* __restrict__ x,
    const float* __restrict__ wq,
    const float* __restrict__ wk,
    const float* __restrict__ wv)
{
    int f = blockIdx.x, b = blockIdx.y;
    extern __shared__ float sm[];
    float* xs = sm;                      // [3][CC][WW+2]
    float* wt = sm + 3*CC*(WW+2);        // [3][MM][CC][9]
    int tid = threadIdx.x;

    for (int idx = tid; idx < 3*CC*(WW+2); idx += 256) {
        int r   = idx / (CC*(WW+2));
        int rem = idx % (CC*(WW+2));
        int c   = rem / (WW+2);
        int w   = rem % (WW+2) - 1;
        int fr  = f + r - 1;
        float v = 0.f;
        if (fr >= 0 && fr < FF && w >= 0 && w < WW)
            v = x[((b*CC + c)*FF + fr)*WW + w];
        xs[idx] = v;
    }
    for (int idx = tid; idx < MM*CC*9; idx += 256) {
        wt[idx]              = wq[idx];
        wt[idx +   MM*CC*9]  = wk[idx];
        wt[idx + 2*MM*CC*9]  = wv[idx];
    }
    __syncthreads();

    for (int o = tid; o < 3*MM*WW; o += 256) {
        int p = o / (MM*WW);
        int m = (o / WW) % MM;
        int w = o % WW;
        const float* wpt = wt + (p*MM + m)*CC*9;
        float acc = 0.f;
        #pragma unroll
        for (int c = 0; c < CC; c++) {
            #pragma unroll
            for (int r = 0; r < 3; r++) {
                const float* xr = xs + (r*CC + c)*(WW+2) + w;
                acc += xr[0]*wpt[c*9 + r*3 + 0];
                acc += xr[1]*wpt[c*9 + r*3 + 1];
                acc += xr[2]*wpt[c*9 + r*3 + 2];
            }
        }
        g_c1[p*BMFW + ((b*MM + m)*FF + f)*WW + w] = acc;
    }
}

// ============================================================
// Kernel 2: batched GEMM, 128x64 tiles, 8x4 microtile.
// ============================================================
__global__ __launch_bounds__(256) void gemm_lin_kernel(
    const float* __restrict__ Aq,
    const float* __restrict__ Ak,
    const float* __restrict__ Av)
{
    __shared__ float As[128*17];
    __shared__ float Bs[16*64];
    int z = blockIdx.z;
    int p = z >> 4;
    int n = z & 15;
    int m = n % MM;
    int g0 = blockIdx.y * 128, w0 = blockIdx.x * 64;
    const float* A = (p == 0) ? Aq : (p == 1) ? Ak : Av;
    const float* Ap = A + m*FF*FF;
    const float* Bp = g_c1  + (size_t)p*BMFW + (size_t)n*FF*WW;
    float*       Cp = g_lin + (size_t)p*BMFW + (size_t)n*FF*WW;
    int tx = threadIdx.x, ty = threadIdx.y;
    int tid = ty*16 + tx;

    float acc[8][4] = {};
    for (int f0 = 0; f0 < FF; f0 += 16) {
        #pragma unroll
        for (int u = 0; u < 2; u++) {
            int idx = tid + u*256;
            int r = idx >> 2;
            int c4 = (idx & 3) * 4;
            float4 a4 = *(const float4*)(Ap + (g0+r)*FF + f0 + c4);
            As[r*17 + c4+0] = a4.x; As[r*17 + c4+1] = a4.y;
            As[r*17 + c4+2] = a4.z; As[r*17 + c4+3] = a4.w;
        }
        {
            int fl = tid >> 4;
            int wl = (tid & 15) * 4;
            *(float4*)(Bs + fl*64 + wl) =
                *(const float4*)(Bp + (f0+fl)*WW + w0 + wl);
        }
        __syncthreads();
        #pragma unroll
        for (int k = 0; k < 16; k++) {
            float a[8];
            #pragma unroll
            for (int i = 0; i < 8; i++) a[i] = As[(ty*8+i)*17 + k];
            float4 b4 = *(const float4*)(Bs + k*64 + tx*4);
            float bf[4] = {b4.x, b4.y, b4.z, b4.w};
            #pragma unroll
            for (int i = 0; i < 8; i++)
                #pragma unroll
                for (int j = 0; j < 4; j++)
                    acc[i][j] += a[i]*bf[j];
        }
        __syncthreads();
    }
    #pragma unroll
    for (int i = 0; i < 8; i++) {
        float4 o4 = make_float4(acc[i][0], acc[i][1], acc[i][2], acc[i][3]);
        *(float4*)(Cp + (g0 + ty*8 + i)*WW + w0 + tx*4) = o4;
    }
}

// ============================================================
// Kernel 3: 1x3 conv across M + rotary, all 3 projections (z).
// ============================================================
__global__ __launch_bounds__(256) void conv2_rot_kernel(
    const float* __restrict__ wq2,
    const float* __restrict__ wk2,
    const float* __restrict__ wv2)
{
    int e = blockIdx.x, b = blockIdx.y, p = blockIdx.z;
    int f0 = 2*e;
    int apply_rot = (p < 2);
    const float* wc2 = (p == 0) ? wq2 : (p == 1) ? wk2 : wv2;
    const float* src = g_lin + (size_t)p*BMFW;
    float*       dst = g_qkv + (size_t)p*BMFW;

    __shared__ float hs[2*MM*(WW+2)];
    __shared__ float wt[MM*MM*3];
    __shared__ float rc[WW], rs[WW];
    int tid = threadIdx.x;

    for (int idx = tid; idx < 2*MM*(WW+2); idx += 256) {
        int rr  = idx / (MM*(WW+2));
        int rem = idx % (MM*(WW+2));
        int mm  = rem / (WW+2);
        int w   = rem % (WW+2) - 1;
        float v = 0.f;
        if (w >= 0 && w < WW)
            v = src[((b*MM + mm)*FF + f0 + rr)*WW + w];
        hs[idx] = v;
    }
    for (int idx = tid; idx < MM*MM*3; idx += 256) wt[idx] = wc2[idx];
    if (apply_rot) {
        int i = e % (HD/2);
        for (int w = tid; w < WW; w += 256) {
            rc[w] = g_rotc[i*WW + w];
            rs[w] = g_rots[i*WW + w];
        }
    }
    __syncthreads();

    for (int o = tid; o < MM*(WW/4); o += 256) {
        int m  = o >> 7;            // WW/4 = 128
        int w4 = (o & 127) * 4;
        float c0[4] = {0.f,0.f,0.f,0.f};
        float c1[4] = {0.f,0.f,0.f,0.f};
        #pragma unroll
        for (int mm = 0; mm < MM; mm++) {
            float k0 = wt[(m*MM+mm)*3+0];
            float k1 = wt[(m*MM+mm)*3+1];
            float k2 = wt[(m*MM+mm)*3+2];
            const float* h0 = hs + mm*(WW+2) + w4;
            const float* h1 = hs + (MM+mm)*(WW+2) + w4;
            float a0=h0[0],a1=h0[1],a2=h0[2],a3=h0[3],a4=h0[4],a5=h0[5];
            c0[0] += a0*k0 + a1*k1 + a2*k2;
            c0[1] += a1*k0 + a2*k1 + a3*k2;
            c0[2] += a2*k0 + a3*k1 + a4*k2;
            c0[3] += a3*k0 + a4*k1 + a5*k2;
            float e0=h1[0],e1=h1[1],e2=h1[2],e3=h1[3],e4=h1[4],e5=h1[5];
            c1[0] += e0*k0 + e1*k1 + e2*k2;
            c1[1] += e1*k0 + e2*k1 + e3*k2;
            c1[2] += e2*k0 + e3*k1 + e4*k2;
            c1[3] += e3*k0 + e4*k1 + e5*k2;
        }
        float4 o0, o1;
        float* po0 = (float*)&o0;
        float* po1 = (float*)&o1;
        if (apply_rot) {
            #pragma unroll
            for (int u = 0; u < 4; u++) {
                float cs = rc[w4+u], sn = rs[w4+u];
                po0[u] = c0[u]*cs - c1[u]*sn;
                po1[u] = c1[u]*cs + c0[u]*sn;
            }
        } else {
            #pragma unroll
            for (int u = 0; u < 4; u++) { po0[u] = c0[u]; po1[u] = c1[u]; }
        }
        *(float4*)(dst + ((size_t)(b*MM + m)*FF + f0    )*WW + w4) = o0;
        *(float4*)(dst + ((size_t)(b*MM + m)*FF + f0 + 1)*WW + w4) = o1;
    }
}

// ============================================================
// Kernel 4: FUSED attention via mma.sync tf32 (m16n8k8).
// 256 threads = 8 warps; each warp owns a 16-row strip.
// S = QK^T: plain tf32 MMA (qk error ~6e-5).
// PV: error-compensated tf32 (P=Ph+Pd, V=Vh+Vd; 3 MMAs).
// P stays in smem (full fp32), warp-local rows only.
// ============================================================
#define KTS 136   // Kt row stride (conflict-free B-frag LDS)
#define PCS 136   // Pch row stride (conflict-free A-frag LDS + STS)

__global__ __launch_bounds__(256, 1) void attn_mma_kernel(
    const float* __restrict__ prev_qk,
    float* __restrict__ qk_out)
{
    int rb = blockIdx.x, t = blockIdx.y;
    int r0 = rb * 128;
    int h = t % HH, m = (t / HH) % MM, b = t / (HH*MM);

    extern __shared__ float smx[];
    float* Kt  = smx;               // [32][KTS]   17.4 KB
    float* Pch = Kt + 32*KTS;       // [128][PCS]  69.6 KB
    float* Vfa = Pch + 128*PCS;     // [16384]     64 KB  (tf32 hi of V, frag order)
    float* Vfd = Vfa + 16384;       // [16384]     64 KB  (tf32 residual of V)

    int tid  = threadIdx.x;
    int lane = tid & 31, wp = tid >> 5;   // 8 warps
    int g = lane >> 2, t4 = lane & 3;
    int rloc = wp*16 + g;                 // local row within 128-row slab

    const float* Qb = g_qkv + 0*BMFW + ((b*MM+m)*FF + h*HD)*WW;
    const float* Kb = g_qkv + 1*BMFW + ((b*MM+m)*FF + h*HD)*WW;
    const float* Vb = g_qkv + 2*BMFW + ((b*MM+m)*FF + h*HD)*WW;
    const float* Pq   = prev_qk + (size_t)t*WW2;
    float*       Sout = qk_out  + (size_t)t*WW2;
    float*       At   = g_at + (size_t)(b*MM+m)*WW*FF + h*HD;

    // ---- Q A-fragments (regs, tf32), k = 32 -> 4 k-tiles ----
    unsigned aq[4][4];
    #pragma unroll
    for (int kt = 0; kt < 4; kt++) {
        int d0 = kt*8 + t4;
        aq[kt][0] = __float_as_uint(to_tf32(Qb[(d0  )*WW + r0 + rloc    ]));
        aq[kt][1] = __float_as_uint(to_tf32(Qb[(d0  )*WW + r0 + rloc + 8]));
        aq[kt][2] = __float_as_uint(to_tf32(Qb[(d0+4)*WW + r0 + rloc    ]));
        aq[kt][3] = __float_as_uint(to_tf32(Qb[(d0+4)*WW + r0 + rloc + 8]));
    }

    // ---- V in fragment order: b0 idx p=0 (k=l&3), b1 p=1 (k=l&3+4) ----
    for (int idx = tid; idx < 16384; idx += 256) {
        int p  = idx & 1;
        int l  = (idx >> 1) & 31;
        int dt = (idx >> 6) & 3;
        int KT = idx >> 8;                // j-tile over full 512
        int j  = KT*8 + (l & 3) + p*4;
        int d  = dt*8 + (l >> 2);
        float v  = Vb[d*WW + j];
        float vh = to_tf32(v);
        Vfa[idx] = vh;
        Vfd[idx] = to_tf32(v - vh);
    }

    float rlo = 0.f, rhi = 0.f;
    float pvacc[4][4];
    #pragma unroll
    for (int dt = 0; dt < 4; dt++)
        #pragma unroll
        for (int q = 0; q < 4; q++) pvacc[dt][q] = 0.f;

    const float scale = 0.0625f;  // 1/sqrt(256)

    for (int cc = 0; cc < 4; cc++) {
        int j0 = cc * 128;
        __syncthreads();   // Kt reusable; Vfa ready (cc=0)

        // ---- stage K chunk (tf32-rounded), coalesced ----
        #pragma unroll
        for (int u = 0; u < 4; u++) {
            int fid = tid + u*256;        // [0,1024)
            int d   = fid >> 5;
            int c4  = (fid & 31) * 4;
            float4 k4 = *(const float4*)(Kb + d*WW + j0 + c4);
            float* kp = Kt + d*KTS + c4;
            kp[0] = to_tf32(k4.x); kp[1] = to_tf32(k4.y);
            kp[2] = to_tf32(k4.z); kp[3] = to_tf32(k4.w);
        }
        __syncthreads();

        // ---- S MMA: strip 16 x 128, 16 n-tiles x 4 k-tiles ----
        float cS[16][4];
        #pragma unroll
        for (int jt = 0; jt < 16; jt++) {
            cS[jt][0] = 0.f; cS[jt][1] = 0.f; cS[jt][2] = 0.f; cS[jt][3] = 0.f;
            #pragma unroll
            for (int kt = 0; kt < 4; kt++) {
                unsigned b0 = __float_as_uint(Kt[(kt*8 + t4    )*KTS + jt*8 + g]);
                unsigned b1 = __float_as_uint(Kt[(kt*8 + t4 + 4)*KTS + jt*8 + g]);
                mma_tf32(cS[jt], aq[kt], b0, b1);
            }
        }

        // ---- epilogue: prev add, Sout, exp -> Pch (fp32), rowsums ----
        #pragma unroll
        for (int jt = 0; jt < 16; jt++) {
            int col = j0 + jt*8 + t4*2;
            size_t off = (size_t)(r0 + rloc)*WW + col;
            float2 pq = *(const float2*)(Pq + off);
            float s0 = fmaf(cS[jt][0], scale, pq.x);
            float s1 = fmaf(cS[jt][1], scale, pq.y);
            *(float2*)(Sout + off) = make_float2(s0, s1);
            float e0 = __expf(s0), e1 = __expf(s1);
            rlo += e0 + e1;
            *(float2*)(Pch + rloc*PCS + jt*8 + t4*2) = make_float2(e0, e1);

            size_t off2 = off + (size_t)8*WW;
            float2 pq2 = *(const float2*)(Pq + off2);
            float s2 = fmaf(cS[jt][2], scale, pq2.x);
            float s3 = fmaf(cS[jt][3], scale, pq2.y);
            *(float2*)(Sout + off2) = make_float2(s2, s3);
            float e2 = __expf(s2), e3 = __expf(s3);
            rhi += e2 + e3;
            *(float2*)(Pch + (rloc + 8)*PCS + jt*8 + t4*2) = make_float2(e2, e3);
        }
        __syncwarp();   // Pch strip rows are warp-local

        // ---- PV MMA (split precision): 16 k-tiles x 4 d-tiles ----
        #pragma unroll 4
        for (int kt2 = 0; kt2 < 16; kt2++) {
            float p0 = Pch[(rloc    )*PCS + kt2*8 + t4    ];
            float p1 = Pch[(rloc + 8)*PCS + kt2*8 + t4    ];
            float p2 = Pch[(rloc    )*PCS + kt2*8 + t4 + 4];
            float p3 = Pch[(rloc + 8)*PCS + kt2*8 + t4 + 4];
            float h0 = to_tf32(p0), h1 = to_tf32(p1);
            float h2 = to_tf32(p2), h3 = to_tf32(p3);
            unsigned ah[4] = { __float_as_uint(h0), __float_as_uint(h1),
                               __float_as_uint(h2), __float_as_uint(h3) };
            unsigned ad[4] = { __float_as_uint(to_tf32(p0 - h0)),
                               __float_as_uint(to_tf32(p1 - h1)),
                               __float_as_uint(to_tf32(p2 - h2)),
                               __float_as_uint(to_tf32(p3 - h3)) };
            int vbase = (cc*16 + kt2)*4*64 + lane*2;
            #pragma unroll
            for (int dt = 0; dt < 4; dt++) {
                float2 bh = *(const float2*)(Vfa + vbase + dt*64);
                float2 bd = *(const float2*)(Vfd + vbase + dt*64);
                unsigned bh0 = __float_as_uint(bh.x), bh1 = __float_as_uint(bh.y);
                unsigned bd0 = __float_as_uint(bd.x), bd1 = __float_as_uint(bd.y);
                mma_tf32(pvacc[dt], ah, bh0, bh1);
                mma_tf32(pvacc[dt], ah, bd0, bd1);
                mma_tf32(pvacc[dt], ad, bh0, bh1);
            }
        }
    }

    // ---- rowsum reduce within quad (lanes sharing g) ----
    rlo += __shfl_xor_sync(0xffffffffu, rlo, 1);
    rlo += __shfl_xor_sync(0xffffffffu, rlo, 2);
    rhi += __shfl_xor_sync(0xffffffffu, rhi, 1);
    rhi += __shfl_xor_sync(0xffffffffu, rhi, 2);
    float ilo = 1.0f / rlo, ihi = 1.0f / rhi;

    // ---- normalize + store A ----
    #pragma unroll
    for (int dt = 0; dt < 4; dt++) {
        *(float2*)(At + (size_t)(r0 + rloc    )*FF + dt*8 + t4*2) =
            make_float2(pvacc[dt][0]*ilo, pvacc[dt][1]*ilo);
        *(float2*)(At + (size_t)(r0 + rloc + 8)*FF + dt*8 + t4*2) =
            make_float2(pvacc[dt][2]*ihi, pvacc[dt][3]*ihi);
    }
}

// ============================================================
// Kernel 5: out projection, 128x64 tiles, 8x4 microtile.
// ============================================================
__global__ __launch_bounds__(256) void gemm_out_kernel(
    const float* __restrict__ A,
    const float* __restrict__ Bt,
    float* __restrict__ Cx)
{
    __shared__ float As[128*17];
    __shared__ float Bs[64*17];
    int n = blockIdx.z;
    int m = n % MM;
    int g0 = blockIdx.y * 128, w0 = blockIdx.x * 64;
    const float* Ap = A  + m*FF*FF;
    const float* Bp = Bt + (size_t)n*WW*FF;
    int tx = threadIdx.x, ty = threadIdx.y;
    int tid = ty*16 + tx;

    float acc[8][4] = {};
    for (int f0 = 0; f0 < FF; f0 += 16) {
        #pragma unroll
        for (int u = 0; u < 2; u++) {
            int idx = tid + u*256;
            int r = idx >> 2;
            int c4 = (idx & 3) * 4;
            float4 a4 = *(const float4*)(Ap + (g0+r)*FF + f0 + c4);
            As[r*17 + c4+0] = a4.x; As[r*17 + c4+1] = a4.y;
            As[r*17 + c4+2] = a4.z; As[r*17 + c4+3] = a4.w;
        }
        {
            int wl = tid >> 2;
            int c4 = (tid & 3) * 4;
            float4 b4 = *(const float4*)(Bp + (size_t)(w0+wl)*FF + f0 + c4);
            Bs[wl*17 + c4+0] = b4.x; Bs[wl*17 + c4+1] = b4.y;
            Bs[wl*17 + c4+2] = b4.z; Bs[wl*17 + c4+3] = b4.w;
        }
        __syncthreads();
        #pragma unroll
        for (int k = 0; k < 16; k++) {
            float a[8], bf[4];
            #pragma unroll
            for (int i = 0; i < 8; i++) a[i]  = As[(ty*8+i)*17 + k];
            #pragma unroll
            for (int j = 0; j < 4; j++) bf[j] = Bs[(tx*4+j)*17 + k];
            #pragma unroll
            for (int i = 0; i < 8; i++)
                #pragma unroll
                for (int j = 0; j < 4; j++)
                    acc[i][j] += a[i]*bf[j];
        }
        __syncthreads();
    }
    #pragma unroll
    for (int i = 0; i < 8; i++) {
        float4 o4 = make_float4(acc[i][0], acc[i][1], acc[i][2], acc[i][3]);
        *(float4*)(Cx + ((size_t)n*FF + g0 + ty*8 + i)*WW + w0 + tx*4) = o4;
    }
}

// ============================================================
extern "C" void kernel_launch(void* const* d_in, const int* in_sizes, int n_in,
                              void* d_out, int out_size)
{
    const float* x       = (const float*)d_in[0];
    const float* prev_qk = (const float*)d_in[1];
    const float* ow      = (const float*)d_in[11];

    float* out_ptr = (float*)d_out;                // (B,M,F,W) first
    float* qk_ptr  = out_ptr + (size_t)BMFW;       // (B,M,H,W,W) second

    float* p_at;
    cudaGetSymbolAddress((void**)&p_at, g_at);

    // rotary table
    rot_table_kernel<<<16, WW>>>();

    // conv1
    int conv1_smem = (3*CC*(WW+2) + 3*MM*CC*9) * 4;
    cudaFuncSetAttribute(conv1_kernel,
        cudaFuncAttributeMaxDynamicSharedMemorySize, conv1_smem);
    conv1_kernel<<<dim3(FF, BB), 256, conv1_smem>>>(
        x, (const float*)d_in[2], (const float*)d_in[5], (const float*)d_in[8]);

    // lin GEMMs
    gemm_lin_kernel<<<dim3(WW/64, FF/128, 3*BB*MM), dim3(16,16)>>>(
        (const float*)d_in[3], (const float*)d_in[6], (const float*)d_in[9]);

    // conv2 (+rotary)
    conv2_rot_kernel<<<dim3(FF/2, BB, 3), 256>>>(
        (const float*)d_in[4], (const float*)d_in[7], (const float*)d_in[10]);

    // fused attention via tensor cores (tf32 mma.sync)
    int attn_smem = (32*KTS + 128*PCS + 2*16384) * 4;   // 218112 B
    cudaFuncSetAttribute(attn_mma_kernel,
        cudaFuncAttributeMaxDynamicSharedMemorySize, attn_smem);
    attn_mma_kernel<<<dim3(4, NT), 256, attn_smem>>>(prev_qk, qk_ptr);

    // output projection
    gemm_out_kernel<<<dim3(WW/64, FF/128, BB*MM), dim3(16,16)>>>(ow, p_at, out_ptr);
}

// round 17
// speedup vs baseline: 1.2575x; 1.0526x over previous
#include <cuda_runtime.h>
#include <math.h>

#define BB 2
#define CC 8
#define MM 8
#define HH 8
#define FF 256
#define WW 512
#define HD 32
#define BMFW (BB*MM*FF*WW)   // 2,097,152
#define NT  (BB*MM*HH)       // 128 attention tiles
#define WW2 (WW*WW)          // 262144

// ---- scratch (static device memory; no allocation) ----
__device__ float g_c1[3*BMFW];     // conv1 outputs for q,k,v
__device__ float g_lin[3*BMFW];    // lin outputs q,k,v
__device__ float g_qkv[3*BMFW];    // q,k,v post conv2(+rotary), layout [b][m][f][w]
__device__ float g_at[BMFW];       // attention out, layout [b][m][w][f]
__device__ float g_rotc[16*WW];
__device__ float g_rots[16*WW];

// ---- tf32 helpers ----
__device__ __forceinline__ float to_tf32(float x) {
    float r;
    asm("cvt.rna.tf32.f32 %0, %1;" : "=f"(r) : "f"(x));
    return r;
}
__device__ __forceinline__ void mma_tf32(float* c, const unsigned* a,
                                         unsigned b0, unsigned b1) {
    asm volatile(
        "mma.sync.aligned.m16n8k8.row.col.f32.tf32.tf32.f32 "
        "{%0,%1,%2,%3}, {%4,%5,%6,%7}, {%8,%9}, {%0,%1,%2,%3};"
        : "+f"(c[0]), "+f"(c[1]), "+f"(c[2]), "+f"(c[3])
        : "r"(a[0]), "r"(a[1]), "r"(a[2]), "r"(a[3]), "r"(b0), "r"(b1));
}

// ============================================================
// Kernel 0: rotary table
// ============================================================
__global__ void rot_table_kernel()
{
    int i = blockIdx.x, w = threadIdx.x;
    float invf = expf(-(float)i * (9.210340371976184f / 16.0f));
    float sn, cs;
    sincosf((float)w * invf, &sn, &cs);
    g_rotc[i*WW + w] = cs;
    g_rots[i*WW + w] = sn;
}

// ============================================================
// Kernel 1: 3x3 conv, 8->8 ch, all three projections at once.
// ============================================================
__global__ __launch_bounds__(256) void conv1_kernel(
    const float* __restrict__ x,
    const float* __restrict__ wq,
    const float* __restrict__ wk,
    const float* __restrict__ wv)
{
    int f = blockIdx.x, b = blockIdx.y;
    extern __shared__ float sm[];
    float* xs = sm;                      // [3][CC][WW+2]
    float* wt = sm + 3*CC*(WW+2);        // [3][MM][CC][9]
    int tid = threadIdx.x;

    for (int idx = tid; idx < 3*CC*(WW+2); idx += 256) {
        int r   = idx / (CC*(WW+2));
        int rem = idx % (CC*(WW+2));
        int c   = rem / (WW+2);
        int w   = rem % (WW+2) - 1;
        int fr  = f + r - 1;
        float v = 0.f;
        if (fr >= 0 && fr < FF && w >= 0 && w < WW)
            v = x[((b*CC + c)*FF + fr)*WW + w];
        xs[idx] = v;
    }
    for (int idx = tid; idx < MM*CC*9; idx += 256) {
        wt[idx]              = wq[idx];
        wt[idx +   MM*CC*9]  = wk[idx];
        wt[idx + 2*MM*CC*9]  = wv[idx];
    }
    __syncthreads();

    for (int o = tid; o < 3*MM*WW; o += 256) {
        int p = o / (MM*WW);
        int m = (o / WW) % MM;
        int w = o % WW;
        const float* wpt = wt + (p*MM + m)*CC*9;
        float acc = 0.f;
        #pragma unroll
        for (int c = 0; c < CC; c++) {
            #pragma unroll
            for (int r = 0; r < 3; r++) {
                const float* xr = xs + (r*CC + c)*(WW+2) + w;
                acc += xr[0]*wpt[c*9 + r*3 + 0];
                acc += xr[1]*wpt[c*9 + r*3 + 1];
                acc += xr[2]*wpt[c*9 + r*3 + 2];
            }
        }
        g_c1[p*BMFW + ((b*MM + m)*FF + f)*WW + w] = acc;
    }
}

// ============================================================
// Kernel 2: batched GEMM, 128x64 tiles, 8x4 microtile.
// ============================================================
__global__ __launch_bounds__(256) void gemm_lin_kernel(
    const float* __restrict__ Aq,
    const float* __restrict__ Ak,
    const float* __restrict__ Av)
{
    __shared__ float As[128*17];
    __shared__ float Bs[16*64];
    int z = blockIdx.z;
    int p = z >> 4;
    int n = z & 15;
    int m = n % MM;
    int g0 = blockIdx.y * 128, w0 = blockIdx.x * 64;
    const float* A = (p == 0) ? Aq : (p == 1) ? Ak : Av;
    const float* Ap = A + m*FF*FF;
    const float* Bp = g_c1  + (size_t)p*BMFW + (size_t)n*FF*WW;
    float*       Cp = g_lin + (size_t)p*BMFW + (size_t)n*FF*WW;
    int tx = threadIdx.x, ty = threadIdx.y;
    int tid = ty*16 + tx;

    float acc[8][4] = {};
    for (int f0 = 0; f0 < FF; f0 += 16) {
        #pragma unroll
        for (int u = 0; u < 2; u++) {
            int idx = tid + u*256;
            int r = idx >> 2;
            int c4 = (idx & 3) * 4;
            float4 a4 = *(const float4*)(Ap + (g0+r)*FF + f0 + c4);
            As[r*17 + c4+0] = a4.x; As[r*17 + c4+1] = a4.y;
            As[r*17 + c4+2] = a4.z; As[r*17 + c4+3] = a4.w;
        }
        {
            int fl = tid >> 4;
            int wl = (tid & 15) * 4;
            *(float4*)(Bs + fl*64 + wl) =
                *(const float4*)(Bp + (f0+fl)*WW + w0 + wl);
        }
        __syncthreads();
        #pragma unroll
        for (int k = 0; k < 16; k++) {
            float a[8];
            #pragma unroll
            for (int i = 0; i < 8; i++) a[i] = As[(ty*8+i)*17 + k];
            float4 b4 = *(const float4*)(Bs + k*64 + tx*4);
            float bf[4] = {b4.x, b4.y, b4.z, b4.w};
            #pragma unroll
            for (int i = 0; i < 8; i++)
                #pragma unroll
                for (int j = 0; j < 4; j++)
                    acc[i][j] += a[i]*bf[j];
        }
        __syncthreads();
    }
    #pragma unroll
    for (int i = 0; i < 8; i++) {
        float4 o4 = make_float4(acc[i][0], acc[i][1], acc[i][2], acc[i][3]);
        *(float4*)(Cp + (g0 + ty*8 + i)*WW + w0 + tx*4) = o4;
    }
}

// ============================================================
// Kernel 3: 1x3 conv across M + rotary, all 3 projections (z).
// ============================================================
__global__ __launch_bounds__(256) void conv2_rot_kernel(
    const float* __restrict__ wq2,
    const float* __restrict__ wk2,
    const float* __restrict__ wv2)
{
    int e = blockIdx.x, b = blockIdx.y, p = blockIdx.z;
    int f0 = 2*e;
    int apply_rot = (p < 2);
    const float* wc2 = (p == 0) ? wq2 : (p == 1) ? wk2 : wv2;
    const float* src = g_lin + (size_t)p*BMFW;
    float*       dst = g_qkv + (size_t)p*BMFW;

    __shared__ float hs[2*MM*(WW+2)];
    __shared__ float wt[MM*MM*3];
    __shared__ float rc[WW], rs[WW];
    int tid = threadIdx.x;

    for (int idx = tid; idx < 2*MM*(WW+2); idx += 256) {
        int rr  = idx / (MM*(WW+2));
        int rem = idx % (MM*(WW+2));
        int mm  = rem / (WW+2);
        int w   = rem % (WW+2) - 1;
        float v = 0.f;
        if (w >= 0 && w < WW)
            v = src[((b*MM + mm)*FF + f0 + rr)*WW + w];
        hs[idx] = v;
    }
    for (int idx = tid; idx < MM*MM*3; idx += 256) wt[idx] = wc2[idx];
    if (apply_rot) {
        int i = e % (HD/2);
        for (int w = tid; w < WW; w += 256) {
            rc[w] = g_rotc[i*WW + w];
            rs[w] = g_rots[i*WW + w];
        }
    }
    __syncthreads();

    for (int o = tid; o < MM*(WW/4); o += 256) {
        int m  = o >> 7;            // WW/4 = 128
        int w4 = (o & 127) * 4;
        float c0[4] = {0.f,0.f,0.f,0.f};
        float c1[4] = {0.f,0.f,0.f,0.f};
        #pragma unroll
        for (int mm = 0; mm < MM; mm++) {
            float k0 = wt[(m*MM+mm)*3+0];
            float k1 = wt[(m*MM+mm)*3+1];
            float k2 = wt[(m*MM+mm)*3+2];
            const float* h0 = hs + mm*(WW+2) + w4;
            const float* h1 = hs + (MM+mm)*(WW+2) + w4;
            float a0=h0[0],a1=h0[1],a2=h0[2],a3=h0[3],a4=h0[4],a5=h0[5];
            c0[0] += a0*k0 + a1*k1 + a2*k2;
            c0[1] += a1*k0 + a2*k1 + a3*k2;
            c0[2] += a2*k0 + a3*k1 + a4*k2;
            c0[3] += a3*k0 + a4*k1 + a5*k2;
            float e0=h1[0],e1=h1[1],e2=h1[2],e3=h1[3],e4=h1[4],e5=h1[5];
            c1[0] += e0*k0 + e1*k1 + e2*k2;
            c1[1] += e1*k0 + e2*k1 + e3*k2;
            c1[2] += e2*k0 + e3*k1 + e4*k2;
            c1[3] += e3*k0 + e4*k1 + e5*k2;
        }
        float4 o0, o1;
        float* po0 = (float*)&o0;
        float* po1 = (float*)&o1;
        if (apply_rot) {
            #pragma unroll
            for (int u = 0; u < 4; u++) {
                float cs = rc[w4+u], sn = rs[w4+u];
                po0[u] = c0[u]*cs - c1[u]*sn;
                po1[u] = c1[u]*cs + c0[u]*sn;
            }
        } else {
            #pragma unroll
            for (int u = 0; u < 4; u++) { po0[u] = c0[u]; po1[u] = c1[u]; }
        }
        *(float4*)(dst + ((size_t)(b*MM + m)*FF + f0    )*WW + w4) = o0;
        *(float4*)(dst + ((size_t)(b*MM + m)*FF + f0 + 1)*WW + w4) = o1;
    }
}

// ============================================================
// Kernel 4: FUSED attention via mma.sync tf32 (m16n8k8).
// 256 threads = 8 warps; warp owns a 16-row strip for MMAs.
// Epilogue restructured: S fragments staged to smem, then a
// block-wide COALESCED pass does prev-add / Sout store / exp /
// P writeback (float4 gmem, conflict-free smem). Row sums kept
// in 16 regs/thread, reduced once at the end.
// ============================================================
#define KTS 136   // Kt row stride
#define PCS 136   // Pch row stride

__global__ __launch_bounds__(256, 1) void attn_mma_kernel(
    const float* __restrict__ prev_qk,
    float* __restrict__ qk_out)
{
    int rb = blockIdx.x, t = blockIdx.y;
    int r0 = rb * 128;
    int h = t % HH, m = (t / HH) % MM, b = t / (HH*MM);

    extern __shared__ float smx[];
    float* Kt  = smx;               // [32][KTS]   17.4 KB
    float* Pch = Kt + 32*KTS;       // [128][PCS]  69.6 KB  (S acc -> P)
    float* Vfa = Pch + 128*PCS;     // [16384]     64 KB  (tf32 hi of V, frag order)
    float* Vfd = Vfa + 16384;       // [16384]     64 KB  (tf32 residual of V)
    float* rsm = Vfd + 16384;       // [128] row sums

    int tid  = threadIdx.x;
    int lane = tid & 31, wp = tid >> 5;   // 8 warps
    int g = lane >> 2, t4 = lane & 3;
    int rloc = wp*16 + g;                 // local row within 128-row slab

    const float* Qb = g_qkv + 0*BMFW + ((b*MM+m)*FF + h*HD)*WW;
    const float* Kb = g_qkv + 1*BMFW + ((b*MM+m)*FF + h*HD)*WW;
    const float* Vb = g_qkv + 2*BMFW + ((b*MM+m)*FF + h*HD)*WW;
    const float* Pq   = prev_qk + (size_t)t*WW2;
    float*       Sout = qk_out  + (size_t)t*WW2;
    float*       At   = g_at + (size_t)(b*MM+m)*WW*FF + h*HD;

    // ---- Q A-fragments (regs, tf32), k = 32 -> 4 k-tiles ----
    unsigned aq[4][4];
    #pragma unroll
    for (int kt = 0; kt < 4; kt++) {
        int d0 = kt*8 + t4;
        aq[kt][0] = __float_as_uint(to_tf32(Qb[(d0  )*WW + r0 + rloc    ]));
        aq[kt][1] = __float_as_uint(to_tf32(Qb[(d0  )*WW + r0 + rloc + 8]));
        aq[kt][2] = __float_as_uint(to_tf32(Qb[(d0+4)*WW + r0 + rloc    ]));
        aq[kt][3] = __float_as_uint(to_tf32(Qb[(d0+4)*WW + r0 + rloc + 8]));
    }

    // ---- V in fragment order: split tf32 hi + residual ----
    for (int idx = tid; idx < 16384; idx += 256) {
        int p  = idx & 1;
        int l  = (idx >> 1) & 31;
        int dt = (idx >> 6) & 3;
        int KT = idx >> 8;                // j-tile over full 512
        int j  = KT*8 + (l & 3) + p*4;
        int d  = dt*8 + (l >> 2);
        float v  = Vb[d*WW + j];
        float vh = to_tf32(v);
        Vfa[idx] = vh;
        Vfd[idx] = to_tf32(v - vh);
    }

    float rsum[16];
    #pragma unroll
    for (int u = 0; u < 16; u++) rsum[u] = 0.f;

    float pvacc[4][4];
    #pragma unroll
    for (int dt = 0; dt < 4; dt++)
        #pragma unroll
        for (int q = 0; q < 4; q++) pvacc[dt][q] = 0.f;

    const float scale = 0.0625f;  // 1/sqrt(256)

    for (int cc = 0; cc < 4; cc++) {
        int j0 = cc * 128;
        __syncthreads();   // PV(cc-1) done with Pch/Kt; Vfa ready (cc=0)

        // ---- stage K chunk (tf32-rounded), coalesced ----
        #pragma unroll
        for (int u = 0; u < 4; u++) {
            int fid = tid + u*256;        // [0,1024)
            int d   = fid >> 5;
            int c4  = (fid & 31) * 4;
            float4 k4 = *(const float4*)(Kb + d*WW + j0 + c4);
            float* kp = Kt + d*KTS + c4;
            kp[0] = to_tf32(k4.x); kp[1] = to_tf32(k4.y);
            kp[2] = to_tf32(k4.z); kp[3] = to_tf32(k4.w);
        }
        __syncthreads();

        // ---- S MMA: strip 16 x 128, 16 n-tiles x 4 k-tiles ----
        float cS[16][4];
        #pragma unroll
        for (int jt = 0; jt < 16; jt++) {
            cS[jt][0] = 0.f; cS[jt][1] = 0.f; cS[jt][2] = 0.f; cS[jt][3] = 0.f;
            #pragma unroll
            for (int kt = 0; kt < 4; kt++) {
                unsigned b0 = __float_as_uint(Kt[(kt*8 + t4    )*KTS + jt*8 + g]);
                unsigned b1 = __float_as_uint(Kt[(kt*8 + t4 + 4)*KTS + jt*8 + g]);
                mma_tf32(cS[jt], aq[kt], b0, b1);
            }
        }

        // ---- stage raw S fragments into Pch ----
        #pragma unroll
        for (int jt = 0; jt < 16; jt++) {
            *(float2*)(Pch + (rloc    )*PCS + jt*8 + t4*2) =
                make_float2(cS[jt][0], cS[jt][1]);
            *(float2*)(Pch + (rloc + 8)*PCS + jt*8 + t4*2) =
                make_float2(cS[jt][2], cS[jt][3]);
        }
        __syncthreads();   // S staged

        // ---- coalesced epilogue: warp wp handles row u*8+wp ----
        #pragma unroll
        for (int u = 0; u < 16; u++) {
            int row = u*8 + wp;
            int col = lane*4;
            float* pp = Pch + row*PCS + col;
            float4 a4 = *(const float4*)pp;
            size_t off = (size_t)(r0 + row)*WW + j0 + col;
            float4 pq4 = __ldg((const float4*)(Pq + off));
            float4 s4;
            s4.x = fmaf(a4.x, scale, pq4.x);
            s4.y = fmaf(a4.y, scale, pq4.y);
            s4.z = fmaf(a4.z, scale, pq4.z);
            s4.w = fmaf(a4.w, scale, pq4.w);
            *(float4*)(Sout + off) = s4;
            float e0 = __expf(s4.x), e1 = __expf(s4.y);
            float e2 = __expf(s4.z), e3 = __expf(s4.w);
            *(float4*)pp = make_float4(e0, e1, e2, e3);
            rsum[u] += e0 + e1 + e2 + e3;
        }
        __syncthreads();   // P ready block-wide

        // ---- PV MMA (split precision): 16 k-tiles x 4 d-tiles ----
        #pragma unroll 4
        for (int kt2 = 0; kt2 < 16; kt2++) {
            float p0 = Pch[(rloc    )*PCS + kt2*8 + t4    ];
            float p1 = Pch[(rloc + 8)*PCS + kt2*8 + t4    ];
            float p2 = Pch[(rloc    )*PCS + kt2*8 + t4 + 4];
            float p3 = Pch[(rloc + 8)*PCS + kt2*8 + t4 + 4];
            float h0 = to_tf32(p0), h1 = to_tf32(p1);
            float h2 = to_tf32(p2), h3 = to_tf32(p3);
            unsigned ah[4] = { __float_as_uint(h0), __float_as_uint(h1),
                               __float_as_uint(h2), __float_as_uint(h3) };
            unsigned ad[4] = { __float_as_uint(to_tf32(p0 - h0)),
                               __float_as_uint(to_tf32(p1 - h1)),
                               __float_as_uint(to_tf32(p2 - h2)),
                               __float_as_uint(to_tf32(p3 - h3)) };
            int vbase = (cc*16 + kt2)*4*64 + lane*2;
            #pragma unroll
            for (int dt = 0; dt < 4; dt++) {
                float2 bh = *(const float2*)(Vfa + vbase + dt*64);
                float2 bd = *(const float2*)(Vfd + vbase + dt*64);
                unsigned bh0 = __float_as_uint(bh.x), bh1 = __float_as_uint(bh.y);
                unsigned bd0 = __float_as_uint(bd.x), bd1 = __float_as_uint(bd.y);
                mma_tf32(pvacc[dt], ah, bh0, bh1);
                mma_tf32(pvacc[dt], ah, bd0, bd1);
                mma_tf32(pvacc[dt], ad, bh0, bh1);
            }
        }
    }

    // ---- final row-sum reduce: warp-reduce each u, lane0 -> rsm ----
    #pragma unroll
    for (int u = 0; u < 16; u++) {
        float s = rsum[u];
        #pragma unroll
        for (int o = 16; o > 0; o >>= 1)
            s += __shfl_xor_sync(0xffffffffu, s, o);
        if (lane == 0) rsm[u*8 + wp] = s;
    }
    __syncthreads();

    float ilo = 1.0f / rsm[rloc];
    float ihi = 1.0f / rsm[rloc + 8];

    // ---- normalize + store A ----
    #pragma unroll
    for (int dt = 0; dt < 4; dt++) {
        *(float2*)(At + (size_t)(r0 + rloc    )*FF + dt*8 + t4*2) =
            make_float2(pvacc[dt][0]*ilo, pvacc[dt][1]*ilo);
        *(float2*)(At + (size_t)(r0 + rloc + 8)*FF + dt*8 + t4*2) =
            make_float2(pvacc[dt][2]*ihi, pvacc[dt][3]*ihi);
    }
}

// ============================================================
// Kernel 5: out projection, 128x64 tiles, 8x4 microtile.
// ============================================================
__global__ __launch_bounds__(256) void gemm_out_kernel(
    const float* __restrict__ A,
    const float* __restrict__ Bt,
    float* __restrict__ Cx)
{
    __shared__ float As[128*17];
    __shared__ float Bs[64*17];
    int n = blockIdx.z;
    int m = n % MM;
    int g0 = blockIdx.y * 128, w0 = blockIdx.x * 64;
    const float* Ap = A  + m*FF*FF;
    const float* Bp = Bt + (size_t)n*WW*FF;
    int tx = threadIdx.x, ty = threadIdx.y;
    int tid = ty*16 + tx;

    float acc[8][4] = {};
    for (int f0 = 0; f0 < FF; f0 += 16) {
        #pragma unroll
        for (int u = 0; u < 2; u++) {
            int idx = tid + u*256;
            int r = idx >> 2;
            int c4 = (idx & 3) * 4;
            float4 a4 = *(const float4*)(Ap + (g0+r)*FF + f0 + c4);
            As[r*17 + c4+0] = a4.x; As[r*17 + c4+1] = a4.y;
            As[r*17 + c4+2] = a4.z; As[r*17 + c4+3] = a4.w;
        }
        {
            int wl = tid >> 2;
            int c4 = (tid & 3) * 4;
            float4 b4 = *(const float4*)(Bp + (size_t)(w0+wl)*FF + f0 + c4);
            Bs[wl*17 + c4+0] = b4.x; Bs[wl*17 + c4+1] = b4.y;
            Bs[wl*17 + c4+2] = b4.z; Bs[wl*17 + c4+3] = b4.w;
        }
        __syncthreads();
        #pragma unroll
        for (int k = 0; k < 16; k++) {
            float a[8], bf[4];
            #pragma unroll
            for (int i = 0; i < 8; i++) a[i]  = As[(ty*8+i)*17 + k];
            #pragma unroll
            for (int j = 0; j < 4; j++) bf[j] = Bs[(tx*4+j)*17 + k];
            #pragma unroll
            for (int i = 0; i < 8; i++)
                #pragma unroll
                for (int j = 0; j < 4; j++)
                    acc[i][j] += a[i]*bf[j];
        }
        __syncthreads();
    }
    #pragma unroll
    for (int i = 0; i < 8; i++) {
        float4 o4 = make_float4(acc[i][0], acc[i][1], acc[i][2], acc[i][3]);
        *(float4*)(Cx + ((size_t)n*FF + g0 + ty*8 + i)*WW + w0 + tx*4) = o4;
    }
}

// ============================================================
extern "C" void kernel_launch(void* const* d_in, const int* in_sizes, int n_in,
                              void* d_out, int out_size)
{
    const float* x       = (const float*)d_in[0];
    const float* prev_qk = (const float*)d_in[1];
    const float* ow      = (const float*)d_in[11];

    float* out_ptr = (float*)d_out;                // (B,M,F,W) first
    float* qk_ptr  = out_ptr + (size_t)BMFW;       // (B,M,H,W,W) second

    float* p_at;
    cudaGetSymbolAddress((void**)&p_at, g_at);

    // rotary table
    rot_table_kernel<<<16, WW>>>();

    // conv1
    int conv1_smem = (3*CC*(WW+2) + 3*MM*CC*9) * 4;
    cudaFuncSetAttribute(conv1_kernel,
        cudaFuncAttributeMaxDynamicSharedMemorySize, conv1_smem);
    conv1_kernel<<<dim3(FF, BB), 256, conv1_smem>>>(
        x, (const float*)d_in[2], (const float*)d_in[5], (const float*)d_in[8]);

    // lin GEMMs
    gemm_lin_kernel<<<dim3(WW/64, FF/128, 3*BB*MM), dim3(16,16)>>>(
        (const float*)d_in[3], (const float*)d_in[6], (const float*)d_in[9]);

    // conv2 (+rotary)
    conv2_rot_kernel<<<dim3(FF/2, BB, 3), 256>>>(
        (const float*)d_in[4], (const float*)d_in[7], (const float*)d_in[10]);

    // fused attention via tensor cores (tf32 mma.sync)
    int attn_smem = (32*KTS + 128*PCS + 2*16384 + 128) * 4;   // 218624 B
    cudaFuncSetAttribute(attn_mma_kernel,
        cudaFuncAttributeMaxDynamicSharedMemorySize, attn_smem);
    attn_mma_kernel<<<dim3(4, NT), 256, attn_smem>>>(prev_qk, qk_ptr);

    // output projection
    gemm_out_kernel<<<dim3(WW/64, FF/128, BB*MM), dim3(16,16)>>>(ow, p_at, out_ptr);
}